// round 14
// baseline (speedup 1.0000x reference)
#include <cuda_runtime.h>
#include <cstdint>

// Problem constants (fixed by setup_inputs)
#define Bb   8
#define Nn   4096
#define Ee   16384
#define Pp   64
#define Dd   256
#define Hh   512
#define MSGm 256
#define UPDu 254
#define STEPS 3

#define SKA  20    // A smem row stride (words)
#define SKB  136   // B smem row stride (words)

// Scratch (device globals per harness allocation rules)
__device__ __align__(128) float g_ns  [(size_t)Bb * Nn * Dd];    // exact state
__device__ __align__(128) float g_nsr [(size_t)Bb * Nn * Dd];    // tf32-rounded state
__device__ __align__(128) float g_p   [(size_t)Bb * Nn * 1024];  // P = nsr @ [We1_top|We1_bot]
__device__ __align__(128) float g_inc [(size_t)Bb * Nn * MSGm];  // messages
__device__ __align__(128) float g_h2  [(size_t)Bb * Nn * Hh];    // rounded node hidden
__device__ __align__(128) float g_We1c[(size_t)Dd * 1024];       // combined+rounded W_e1
__device__ __align__(128) float g_We2r[(size_t)Hh * MSGm];
__device__ __align__(128) float g_Wn1r[(size_t)(Dd+MSGm) * Hh];
__device__ __align__(128) float g_Wn2r[(size_t)Hh * 256];        // padded 254 -> 256

// ---------------------------------------------------------------------------
__device__ __forceinline__ uint32_t f2tf(float x) {
    uint32_t u;
    asm("cvt.rna.tf32.f32 %0, %1;" : "=r"(u) : "f"(x));
    return u;
}
__device__ __forceinline__ float rndf(float x) { return __uint_as_float(f2tf(x)); }

__device__ __forceinline__ void mma8(float* c, uint32_t a0, uint32_t a1,
                                     uint32_t a2, uint32_t a3,
                                     uint32_t b0, uint32_t b1) {
    asm volatile(
        "mma.sync.aligned.m16n8k8.row.col.f32.tf32.tf32.f32 "
        "{%0,%1,%2,%3}, {%4,%5,%6,%7}, {%8,%9}, {%0,%1,%2,%3};"
        : "+f"(c[0]), "+f"(c[1]), "+f"(c[2]), "+f"(c[3])
        : "r"(a0), "r"(a1), "r"(a2), "r"(a3), "r"(b0), "r"(b1));
}

__device__ __forceinline__ void ldsm4(uint32_t& r0, uint32_t& r1,
                                      uint32_t& r2, uint32_t& r3, uint32_t addr) {
    asm volatile("ldmatrix.sync.aligned.m8n8.x4.shared.b16 {%0,%1,%2,%3}, [%4];"
                 : "=r"(r0), "=r"(r1), "=r"(r2), "=r"(r3) : "r"(addr));
}

__device__ __forceinline__ void cpa16(uint32_t dst, const float* src) {
    asm volatile("cp.async.ca.shared.global [%0], [%1], 16;"
                 :: "r"(dst), "l"(src));
}
#define CP_COMMIT asm volatile("cp.async.commit_group;")
#define CP_WAIT1  asm volatile("cp.async.wait_group 1;")
#define CP_WAIT0  asm volatile("cp.async.wait_group 0;")

// ---------------------------------------------------------------------------
// Prologue / utility kernels
__global__ void k_round(const float* __restrict__ src, float* __restrict__ dst, int n) {
    int i = blockIdx.x * blockDim.x + threadIdx.x;
    if (i < n) dst[i] = rndf(src[i]);
}

__global__ void k_make_we1c(const float* __restrict__ We1) {
    int i = blockIdx.x * blockDim.x + threadIdx.x;   // over Dd*1024
    if (i < Dd * 1024) {
        int k = i >> 10, j = i & 1023;
        float v = (j < Hh) ? We1[k * Hh + j] : We1[(Dd + k) * Hh + (j - Hh)];
        g_We1c[i] = rndf(v);
    }
}

__global__ void k_round_pad_wn2(const float* __restrict__ src) {
    int i = blockIdx.x * blockDim.x + threadIdx.x;   // over Hh*256
    if (i < Hh * 256) {
        int r = i >> 8, c = i & 255;
        g_Wn2r[i] = (c < UPDu) ? rndf(src[r * UPDu + c]) : 0.f;
    }
}

__global__ void k_copy_ns(const float* __restrict__ src) {
    size_t i = (size_t)blockIdx.x * blockDim.x + threadIdx.x;
    if (i < (size_t)Bb * Nn * Dd) {
        float v = src[i];
        g_ns[i]  = v;
        g_nsr[i] = rndf(v);
    }
}

__global__ void k_zero_inc() {
    size_t i = (size_t)blockIdx.x * blockDim.x + threadIdx.x;
    if (i < ((size_t)Bb * Nn * MSGm) / 4)
        ((float4*)g_inc)[i] = make_float4(0.f, 0.f, 0.f, 0.f);
}

__global__ void k_round_inc() {
    size_t i = (size_t)blockIdx.x * blockDim.x + threadIdx.x;
    if (i < (size_t)Bb * Nn * MSGm) g_inc[i] = rndf(g_inc[i]);
}

// ---------------------------------------------------------------------------
// GEMM framework: 256 threads = 8 warps; block tile 128x128, K-step 16,
// 2-stage cp.async; warp tile 64x32 = 4x4 m16n8k8.

#define GEMM_PROLOG                                                      \
    const int tid  = threadIdx.x;                                        \
    const int lane = tid & 31;                                           \
    const int warp = tid >> 5;                                           \
    const int grp  = lane >> 2;                                          \
    const int tig  = lane & 3;                                           \
    const int wM   = (warp & 1) * 64;                                    \
    const int wN   = (warp >> 1) * 32;                                   \
    const int ar   = tid >> 1;                                           \
    const int akq  = (tid & 1) * 8;                                      \
    const int bkr  = tid >> 4;                                           \
    const int bnq  = (tid & 15) * 8;                                     \
    const int lrow = lane & 15;                                          \
    const int lcol = (lane >> 4) * 4;                                    \
    const uint32_t sA = (uint32_t)__cvta_generic_to_shared(&As[0][0][0]);\
    const uint32_t sB = (uint32_t)__cvta_generic_to_shared(&Bs[0][0][0]);\
    float acc[4][4][4];                                                  \
    _Pragma("unroll") for (int i = 0; i < 4; i++)                        \
    _Pragma("unroll") for (int j = 0; j < 4; j++)                        \
    _Pragma("unroll") for (int q = 0; q < 4; q++) acc[i][j][q] = 0.f;

#define A_ADDR(st, m, k) (sA + (((st) * 128 + (m)) * SKA + (k)) * 4u)
#define B_ADDR(st, k, n) (sB + (((st) * 16  + (k)) * SKB + (n)) * 4u)

#define COMPUTE(st)                                                      \
    _Pragma("unroll") for (int kb = 0; kb < 16; kb += 8) {               \
        uint32_t af[4][4], bf[4][2];                                     \
        _Pragma("unroll") for (int mt = 0; mt < 4; mt++)                 \
            ldsm4(af[mt][0], af[mt][1], af[mt][2], af[mt][3],            \
                  A_ADDR(st, wM + mt * 16 + lrow, kb + lcol));           \
        _Pragma("unroll") for (int nt = 0; nt < 4; nt++) {               \
            int cc = wN + nt * 8 + grp;                                  \
            bf[nt][0] = Bs[st][kb + tig][cc];                            \
            bf[nt][1] = Bs[st][kb + tig + 4][cc];                        \
        }                                                                \
        _Pragma("unroll") for (int mt = 0; mt < 4; mt++)                 \
        _Pragma("unroll") for (int nt = 0; nt < 4; nt++)                 \
            mma8(acc[mt][nt], af[mt][0], af[mt][1], af[mt][2],           \
                 af[mt][3], bf[nt][0], bf[nt][1]);                       \
    }

#define PIPELINE(NITER, LOADER)                                          \
    LOADER(0, 0);                                                        \
    CP_COMMIT;                                                           \
    for (int it = 0; it < (NITER); it++) {                               \
        if (it + 1 < (NITER)) {                                          \
            LOADER((it + 1) & 1, (it + 1) * 16);                         \
            CP_COMMIT;                                                   \
            CP_WAIT1;                                                    \
        } else {                                                         \
            CP_WAIT0;                                                    \
        }                                                                \
        __syncthreads();                                                 \
        COMPUTE(it & 1);                                                 \
        __syncthreads();                                                 \
    }

#define SMEM_TILES                                                       \
    __shared__ uint32_t As[2][128][SKA];                                 \
    __shared__ uint32_t Bs[2][16][SKB];

// ---------------------------------------------------------------------------
// Node-projection GEMM: g_p = g_nsr @ g_We1c
// M = 32768, N = 1024, K = 256
__global__ __launch_bounds__(256, 2)
void k_pre()
{
    SMEM_TILES;
    GEMM_PROLOG;

    const int rowBase = blockIdx.y * 128;
    const int colBase = blockIdx.x * 128;

#define LOAD_P(st, k0)                                                   \
    {                                                                    \
        _Pragma("unroll") for (int q = 0; q < 2; q++)                    \
            cpa16(A_ADDR(st, ar, akq + q * 4),                           \
                  g_nsr + (size_t)(rowBase + ar) * Dd + (k0) + akq + q * 4); \
        _Pragma("unroll") for (int q = 0; q < 2; q++)                    \
            cpa16(B_ADDR(st, bkr, bnq + q * 4),                          \
                  g_We1c + (size_t)((k0) + bkr) * 1024 + colBase + bnq + q * 4); \
    }

    PIPELINE(16, LOAD_P);

#pragma unroll
    for (int mt = 0; mt < 4; mt++) {
        int r0 = rowBase + wM + mt * 16 + grp;
#pragma unroll
        for (int nt = 0; nt < 4; nt++) {
            int c0 = colBase + wN + nt * 8 + tig * 2;
            float* a = acc[mt][nt];
            *(float2*)(g_p + (size_t)r0 * 1024 + c0)       = make_float2(a[0], a[1]);
            *(float2*)(g_p + (size_t)(r0 + 8) * 1024 + c0) = make_float2(a[2], a[3]);
        }
    }
}

// ---------------------------------------------------------------------------
// Fused edge MLP + scatter:
//   h = rna(relu(P[src] + P[snk] + be1)) ; msgs = h @ We2r + be2
//   atomicAdd msgs into g_inc[snk]
// M = B*E = 131072, N = 256, K = 512
__global__ __launch_bounds__(256, 2)
void k_edge2f(const float* __restrict__ be1, const float* __restrict__ be2,
              const int* __restrict__ esrc, const int* __restrict__ esnk)
{
    SMEM_TILES;
    __shared__ int sIdx[2][128];

    GEMM_PROLOG;

    const int rowBase = blockIdx.y * 128;
    const int colBase = blockIdx.x * 128;
    const int b  = rowBase >> 14;
    const int e0 = rowBase & (Ee - 1);

    if (tid < 128)      sIdx[0][tid]       = esrc[e0 + tid];
    else                sIdx[1][tid - 128] = esnk[e0 + tid - 128];
    __syncthreads();

    const float* Pb = g_p + (size_t)b * Nn * 1024;
    const size_t srcRow = (size_t)sIdx[0][ar] * 1024;
    const size_t snkRow = (size_t)sIdx[1][ar] * 1024 + 512;

    float4 u0, u1, v0, v1;

#define ISSUE_EF(k0)                                                     \
    {                                                                    \
        u0 = *(const float4*)(Pb + srcRow + (k0) + akq);                 \
        u1 = *(const float4*)(Pb + srcRow + (k0) + akq + 4);             \
        v0 = *(const float4*)(Pb + snkRow + (k0) + akq);                 \
        v1 = *(const float4*)(Pb + snkRow + (k0) + akq + 4);             \
    }

#define COMMIT_EF(st, k0)                                                \
    {                                                                    \
        float4 b0 = *(const float4*)(be1 + (k0) + akq);                  \
        float4 b1 = *(const float4*)(be1 + (k0) + akq + 4);              \
        uint32_t* dst = (uint32_t*)&As[st][ar][akq];                     \
        dst[0] = f2tf(fmaxf(u0.x + v0.x + b0.x, 0.f));                   \
        dst[1] = f2tf(fmaxf(u0.y + v0.y + b0.y, 0.f));                   \
        dst[2] = f2tf(fmaxf(u0.z + v0.z + b0.z, 0.f));                   \
        dst[3] = f2tf(fmaxf(u0.w + v0.w + b0.w, 0.f));                   \
        dst[4] = f2tf(fmaxf(u1.x + v1.x + b1.x, 0.f));                   \
        dst[5] = f2tf(fmaxf(u1.y + v1.y + b1.y, 0.f));                   \
        dst[6] = f2tf(fmaxf(u1.z + v1.z + b1.z, 0.f));                   \
        dst[7] = f2tf(fmaxf(u1.w + v1.w + b1.w, 0.f));                   \
    }

#define LOADB_EF(st, k0)                                                 \
    _Pragma("unroll") for (int q = 0; q < 2; q++)                        \
        cpa16(B_ADDR(st, bkr, bnq + q * 4),                              \
              g_We2r + (size_t)((k0) + bkr) * MSGm + colBase + bnq + q * 4);

    ISSUE_EF(0);
    LOADB_EF(0, 0);
    CP_COMMIT;
    COMMIT_EF(0, 0);

    for (int it = 0; it < 32; it++) {
        if (it + 1 < 32) {
            ISSUE_EF((it + 1) * 16);
            LOADB_EF((it + 1) & 1, (it + 1) * 16);
            CP_COMMIT;
            CP_WAIT1;
        } else {
            CP_WAIT0;
        }
        __syncthreads();
        COMPUTE(it & 1);
        if (it + 1 < 32) COMMIT_EF((it + 1) & 1, (it + 1) * 16);
        __syncthreads();
    }

    float* incb = g_inc + (size_t)b * Nn * MSGm;
#pragma unroll
    for (int mt = 0; mt < 4; mt++) {
        int r0 = wM + mt * 16 + grp;
        int s0 = sIdx[1][r0], s1 = sIdx[1][r0 + 8];
#pragma unroll
        for (int nt = 0; nt < 4; nt++) {
            int c0 = colBase + wN + nt * 8 + tig * 2;
            float b0 = be2[c0], b1 = be2[c0 + 1];
            float* a = acc[mt][nt];
            float* p0 = incb + (size_t)s0 * MSGm + c0;
            float* p1 = incb + (size_t)s1 * MSGm + c0;
            atomicAdd(p0,     a[0] + b0);
            atomicAdd(p0 + 1, a[1] + b1);
            atomicAdd(p1,     a[2] + b0);
            atomicAdd(p1 + 1, a[3] + b1);
        }
    }
}

// ---------------------------------------------------------------------------
// Node MLP layer 1: g_h2 = rna(relu(concat(g_inc, g_nsr) @ Wn1r + b_n1))
// M = 32768, N = 512, K = 512
__global__ __launch_bounds__(256, 2)
void k_node1(const float* __restrict__ bn1)
{
    SMEM_TILES;
    GEMM_PROLOG;

    const int rowBase = blockIdx.y * 128;
    const int colBase = blockIdx.x * 128;

#define LOAD_N1(st, k0)                                                  \
    {                                                                    \
        _Pragma("unroll") for (int q = 0; q < 2; q++) {                  \
            int kg = (k0) + akq + q * 4;                                 \
            const float* src = (kg < MSGm)                               \
                ? (g_inc + (size_t)(rowBase + ar) * MSGm + kg)           \
                : (g_nsr + (size_t)(rowBase + ar) * Dd + (kg - MSGm));   \
            cpa16(A_ADDR(st, ar, akq + q * 4), src);                     \
        }                                                                \
        _Pragma("unroll") for (int q = 0; q < 2; q++)                    \
            cpa16(B_ADDR(st, bkr, bnq + q * 4),                          \
                  g_Wn1r + (size_t)((k0) + bkr) * Hh + colBase + bnq + q * 4); \
    }

    PIPELINE(32, LOAD_N1);

#pragma unroll
    for (int mt = 0; mt < 4; mt++) {
        int r0 = rowBase + wM + mt * 16 + grp;
#pragma unroll
        for (int nt = 0; nt < 4; nt++) {
            int c0 = colBase + wN + nt * 8 + tig * 2;
            float b0 = bn1[c0], b1 = bn1[c0 + 1];
            float* a = acc[mt][nt];
            *(float2*)(g_h2 + (size_t)r0 * Hh + c0) =
                make_float2(rndf(fmaxf(a[0] + b0, 0.f)), rndf(fmaxf(a[1] + b1, 0.f)));
            *(float2*)(g_h2 + (size_t)(r0 + 8) * Hh + c0) =
                make_float2(rndf(fmaxf(a[2] + b0, 0.f)), rndf(fmaxf(a[3] + b1, 0.f)));
        }
    }
}

// ---------------------------------------------------------------------------
// Node MLP layer 2 + in-place update
// M = 32768, N = 254 (padded 256), K = 512
__global__ __launch_bounds__(256, 2)
void k_node2(const float* __restrict__ bn2)
{
    SMEM_TILES;
    GEMM_PROLOG;

    const int rowBase = blockIdx.y * 128;
    const int colBase = blockIdx.x * 128;

    const float* Ag = g_h2 + (size_t)rowBase * Hh;

#define LOAD_N2(st, k0)                                                  \
    {                                                                    \
        _Pragma("unroll") for (int q = 0; q < 2; q++)                    \
            cpa16(A_ADDR(st, ar, akq + q * 4),                           \
                  Ag + (size_t)ar * Hh + (k0) + akq + q * 4);            \
        _Pragma("unroll") for (int q = 0; q < 2; q++)                    \
            cpa16(B_ADDR(st, bkr, bnq + q * 4),                          \
                  g_Wn2r + (size_t)((k0) + bkr) * 256 + colBase + bnq + q * 4); \
    }

    PIPELINE(32, LOAD_N2);

#pragma unroll
    for (int mt = 0; mt < 4; mt++) {
        int r0 = rowBase + wM + mt * 16 + grp;
#pragma unroll
        for (int nt = 0; nt < 4; nt++) {
            int c0 = colBase + wN + nt * 8 + tig * 2;
            float* a = acc[mt][nt];
#pragma unroll
            for (int h = 0; h < 2; h++) {
                int c = c0 + h;
                if (c < UPDu) {
                    float bb = bn2[c];
                    size_t i0 = (size_t)r0 * Dd + 2 + c;
                    size_t i1 = (size_t)(r0 + 8) * Dd + 2 + c;
                    float v0 = g_ns[i0] + a[h]     + bb;
                    float v1 = g_ns[i1] + a[2 + h] + bb;
                    g_ns[i0] = v0;  g_nsr[i0] = rndf(v0);
                    g_ns[i1] = v1;  g_nsr[i1] = rndf(v1);
                }
            }
        }
    }
}

// ---------------------------------------------------------------------------
// Extraction: out[b,p,d] = sum_n attn[b,p,n] * ns[b,n,d]; 8 p's per CTA.
__global__ __launch_bounds__(256)
void k_extract(const float* __restrict__ attn, float* __restrict__ out)
{
    const int pg = blockIdx.x;   // p group: p = pg*8 .. pg*8+7
    const int b  = blockIdx.y;
    const int d  = threadIdx.x;

    const float* nsb = g_ns + (size_t)b * Nn * Dd;

    __shared__ float sa[8][256];
    float acc[8];
#pragma unroll
    for (int pp = 0; pp < 8; pp++) acc[pp] = 0.f;

    for (int n0 = 0; n0 < Nn; n0 += 256) {
        __syncthreads();
#pragma unroll
        for (int pp = 0; pp < 8; pp++)
            sa[pp][d] = attn[((size_t)b * Pp + pg * 8 + pp) * Nn + n0 + d];
        __syncthreads();
#pragma unroll 4
        for (int n = 0; n < 256; n++) {
            float x = nsb[(size_t)(n0 + n) * Dd + d];
#pragma unroll
            for (int pp = 0; pp < 8; pp++)
                acc[pp] = fmaf(sa[pp][n], x, acc[pp]);
        }
    }

#pragma unroll
    for (int pp = 0; pp < 8; pp++)
        out[((size_t)b * Pp + pg * 8 + pp) * Dd + d] = acc[pp];
}

// ---------------------------------------------------------------------------
extern "C" void kernel_launch(void* const* d_in, const int* in_sizes, int n_in,
                              void* d_out, int out_size)
{
    const float* nodes = (const float*)d_in[0];
    const float* attn  = (const float*)d_in[1];
    const float* We1   = (const float*)d_in[2];
    const float* be1   = (const float*)d_in[3];
    const float* We2   = (const float*)d_in[4];
    const float* be2   = (const float*)d_in[5];
    const float* Wn1   = (const float*)d_in[6];
    const float* bn1   = (const float*)d_in[7];
    const float* Wn2   = (const float*)d_in[8];
    const float* bn2   = (const float*)d_in[9];
    const int*   esrc  = (const int*)d_in[10];
    const int*   esnk  = (const int*)d_in[11];
    float* out = (float*)d_out;

    float* dWe2r; cudaGetSymbolAddress((void**)&dWe2r, g_We2r);
    float* dWn1r; cudaGetSymbolAddress((void**)&dWn1r, g_Wn1r);

    // Prologue: combined/rounded weights + state copies
    k_make_we1c<<<(Dd * 1024 + 255) / 256, 256>>>(We1);
    k_round<<<(Hh * MSGm + 255) / 256, 256>>>(We2, dWe2r, Hh * MSGm);
    k_round<<<((Dd + MSGm) * Hh + 255) / 256, 256>>>(Wn1, dWn1r, (Dd + MSGm) * Hh);
    k_round_pad_wn2<<<(Hh * 256 + 255) / 256, 256>>>(Wn2);
    k_copy_ns<<<(Bb * Nn * Dd + 255) / 256, 256>>>(nodes);

    for (int s = 0; s < STEPS; s++) {
        k_zero_inc<<<8192, 256>>>();
        k_pre<<<dim3(1024 / 128, (Bb * Nn) / 128), 256>>>();
        k_edge2f<<<dim3(MSGm / 128, (Bb * Ee) / 128), 256>>>(be1, be2, esrc, esnk);
        k_round_inc<<<(Bb * Nn * MSGm + 255) / 256, 256>>>();
        k_node1<<<dim3(Hh / 128, (Bb * Nn) / 128), 256>>>(bn1);
        k_node2<<<dim3(2, (Bb * Nn) / 128), 256>>>(bn2);
    }

    k_extract<<<dim3(Pp / 8, Bb), 256>>>(attn, out);
}

// round 16
// speedup vs baseline: 1.1477x; 1.1477x over previous
#include <cuda_runtime.h>
#include <cstdint>

// Problem constants (fixed by setup_inputs)
#define Bb   8
#define Nn   4096
#define Ee   16384
#define Pp   64
#define Dd   256
#define Hh   512
#define MSGm 256
#define UPDu 254
#define STEPS 3

#define SKA  20    // A smem row stride (words)
#define SKB  136   // B smem row stride (words)

// Scratch (device globals per harness allocation rules)
__device__ __align__(128) float g_ns  [(size_t)Bb * Nn * Dd];    // exact state
__device__ __align__(128) float g_nsr [(size_t)Bb * Nn * Dd];    // tf32-rounded state
__device__ __align__(128) float g_p   [(size_t)Bb * Nn * 1024];  // P = nsr @ [We1_top|We1_bot]
__device__ __align__(128) float g_inc [(size_t)Bb * Nn * MSGm];  // messages
__device__ __align__(128) float g_h2  [(size_t)Bb * Nn * Hh];    // rounded node hidden
__device__ __align__(128) float g_We1c[(size_t)Dd * 1024];       // combined+rounded W_e1
__device__ __align__(128) float g_We2r[(size_t)Hh * MSGm];
__device__ __align__(128) float g_Wn1r[(size_t)(Dd+MSGm) * Hh];
__device__ __align__(128) float g_Wn2r[(size_t)Hh * 256];        // padded 254 -> 256

// ---------------------------------------------------------------------------
__device__ __forceinline__ uint32_t f2tf(float x) {
    uint32_t u;
    asm("cvt.rna.tf32.f32 %0, %1;" : "=r"(u) : "f"(x));
    return u;
}
__device__ __forceinline__ float rndf(float x) { return __uint_as_float(f2tf(x)); }

__device__ __forceinline__ void mma8(float* c, uint32_t a0, uint32_t a1,
                                     uint32_t a2, uint32_t a3,
                                     uint32_t b0, uint32_t b1) {
    asm volatile(
        "mma.sync.aligned.m16n8k8.row.col.f32.tf32.tf32.f32 "
        "{%0,%1,%2,%3}, {%4,%5,%6,%7}, {%8,%9}, {%0,%1,%2,%3};"
        : "+f"(c[0]), "+f"(c[1]), "+f"(c[2]), "+f"(c[3])
        : "r"(a0), "r"(a1), "r"(a2), "r"(a3), "r"(b0), "r"(b1));
}

__device__ __forceinline__ void ldsm4(uint32_t& r0, uint32_t& r1,
                                      uint32_t& r2, uint32_t& r3, uint32_t addr) {
    asm volatile("ldmatrix.sync.aligned.m8n8.x4.shared.b16 {%0,%1,%2,%3}, [%4];"
                 : "=r"(r0), "=r"(r1), "=r"(r2), "=r"(r3) : "r"(addr));
}

__device__ __forceinline__ void cpa16(uint32_t dst, const float* src) {
    asm volatile("cp.async.ca.shared.global [%0], [%1], 16;"
                 :: "r"(dst), "l"(src));
}
#define CP_COMMIT asm volatile("cp.async.commit_group;")
#define CP_WAIT1  asm volatile("cp.async.wait_group 1;")
#define CP_WAIT0  asm volatile("cp.async.wait_group 0;")

// ---------------------------------------------------------------------------
// Prologue / utility kernels
__global__ void k_round(const float* __restrict__ src, float* __restrict__ dst, int n) {
    int i = blockIdx.x * blockDim.x + threadIdx.x;
    if (i < n) dst[i] = rndf(src[i]);
}

__global__ void k_make_we1c(const float* __restrict__ We1) {
    int i = blockIdx.x * blockDim.x + threadIdx.x;   // over Dd*1024
    if (i < Dd * 1024) {
        int k = i >> 10, j = i & 1023;
        float v = (j < Hh) ? We1[k * Hh + j] : We1[(Dd + k) * Hh + (j - Hh)];
        g_We1c[i] = rndf(v);
    }
}

__global__ void k_round_pad_wn2(const float* __restrict__ src) {
    int i = blockIdx.x * blockDim.x + threadIdx.x;   // over Hh*256
    if (i < Hh * 256) {
        int r = i >> 8, c = i & 255;
        g_Wn2r[i] = (c < UPDu) ? rndf(src[r * UPDu + c]) : 0.f;
    }
}

__global__ void k_copy_ns(const float* __restrict__ src) {
    size_t i = (size_t)blockIdx.x * blockDim.x + threadIdx.x;
    if (i < (size_t)Bb * Nn * Dd) {
        float v = src[i];
        g_ns[i]  = v;
        g_nsr[i] = rndf(v);
    }
}

__global__ void k_zero_inc() {
    size_t i = (size_t)blockIdx.x * blockDim.x + threadIdx.x;
    if (i < ((size_t)Bb * Nn * MSGm) / 4)
        ((float4*)g_inc)[i] = make_float4(0.f, 0.f, 0.f, 0.f);
}

__global__ void k_round_inc() {
    size_t i = (size_t)blockIdx.x * blockDim.x + threadIdx.x;
    if (i < (size_t)Bb * Nn * MSGm) g_inc[i] = rndf(g_inc[i]);
}

__global__ void k_zero_out(float* __restrict__ out) {
    int i = blockIdx.x * blockDim.x + threadIdx.x;
    if (i < Bb * Pp * Dd) out[i] = 0.f;
}

// ---------------------------------------------------------------------------
// GEMM framework: 256 threads = 8 warps; block tile 128x128, K-step 16,
// 2-stage cp.async; warp tile 64x32 = 4x4 m16n8k8.

#define GEMM_PROLOG                                                      \
    const int tid  = threadIdx.x;                                        \
    const int lane = tid & 31;                                           \
    const int warp = tid >> 5;                                           \
    const int grp  = lane >> 2;                                          \
    const int tig  = lane & 3;                                           \
    const int wM   = (warp & 1) * 64;                                    \
    const int wN   = (warp >> 1) * 32;                                   \
    const int ar   = tid >> 1;                                           \
    const int akq  = (tid & 1) * 8;                                      \
    const int bkr  = tid >> 4;                                           \
    const int bnq  = (tid & 15) * 8;                                     \
    const int lrow = lane & 15;                                          \
    const int lcol = (lane >> 4) * 4;                                    \
    const uint32_t sA = (uint32_t)__cvta_generic_to_shared(&As[0][0][0]);\
    const uint32_t sB = (uint32_t)__cvta_generic_to_shared(&Bs[0][0][0]);\
    float acc[4][4][4];                                                  \
    _Pragma("unroll") for (int i = 0; i < 4; i++)                        \
    _Pragma("unroll") for (int j = 0; j < 4; j++)                        \
    _Pragma("unroll") for (int q = 0; q < 4; q++) acc[i][j][q] = 0.f;

#define A_ADDR(st, m, k) (sA + (((st) * 128 + (m)) * SKA + (k)) * 4u)
#define B_ADDR(st, k, n) (sB + (((st) * 16  + (k)) * SKB + (n)) * 4u)

#define COMPUTE(st)                                                      \
    _Pragma("unroll") for (int kb = 0; kb < 16; kb += 8) {               \
        uint32_t af[4][4], bf[4][2];                                     \
        _Pragma("unroll") for (int mt = 0; mt < 4; mt++)                 \
            ldsm4(af[mt][0], af[mt][1], af[mt][2], af[mt][3],            \
                  A_ADDR(st, wM + mt * 16 + lrow, kb + lcol));           \
        _Pragma("unroll") for (int nt = 0; nt < 4; nt++) {               \
            int cc = wN + nt * 8 + grp;                                  \
            bf[nt][0] = Bs[st][kb + tig][cc];                            \
            bf[nt][1] = Bs[st][kb + tig + 4][cc];                        \
        }                                                                \
        _Pragma("unroll") for (int mt = 0; mt < 4; mt++)                 \
        _Pragma("unroll") for (int nt = 0; nt < 4; nt++)                 \
            mma8(acc[mt][nt], af[mt][0], af[mt][1], af[mt][2],           \
                 af[mt][3], bf[nt][0], bf[nt][1]);                       \
    }

#define PIPELINE(NITER, LOADER)                                          \
    LOADER(0, 0);                                                        \
    CP_COMMIT;                                                           \
    for (int it = 0; it < (NITER); it++) {                               \
        if (it + 1 < (NITER)) {                                          \
            LOADER((it + 1) & 1, (it + 1) * 16);                         \
            CP_COMMIT;                                                   \
            CP_WAIT1;                                                    \
        } else {                                                         \
            CP_WAIT0;                                                    \
        }                                                                \
        __syncthreads();                                                 \
        COMPUTE(it & 1);                                                 \
        __syncthreads();                                                 \
    }

#define SMEM_TILES                                                       \
    __shared__ uint32_t As[2][128][SKA];                                 \
    __shared__ uint32_t Bs[2][16][SKB];

// ---------------------------------------------------------------------------
// Node-projection GEMM: g_p = g_nsr @ g_We1c
// M = 32768, N = 1024, K = 256
__global__ __launch_bounds__(256, 2)
void k_pre()
{
    SMEM_TILES;
    GEMM_PROLOG;

    const int rowBase = blockIdx.y * 128;
    const int colBase = blockIdx.x * 128;

#define LOAD_P(st, k0)                                                   \
    {                                                                    \
        _Pragma("unroll") for (int q = 0; q < 2; q++)                    \
            cpa16(A_ADDR(st, ar, akq + q * 4),                           \
                  g_nsr + (size_t)(rowBase + ar) * Dd + (k0) + akq + q * 4); \
        _Pragma("unroll") for (int q = 0; q < 2; q++)                    \
            cpa16(B_ADDR(st, bkr, bnq + q * 4),                          \
                  g_We1c + (size_t)((k0) + bkr) * 1024 + colBase + bnq + q * 4); \
    }

    PIPELINE(16, LOAD_P);

#pragma unroll
    for (int mt = 0; mt < 4; mt++) {
        int r0 = rowBase + wM + mt * 16 + grp;
#pragma unroll
        for (int nt = 0; nt < 4; nt++) {
            int c0 = colBase + wN + nt * 8 + tig * 2;
            float* a = acc[mt][nt];
            *(float2*)(g_p + (size_t)r0 * 1024 + c0)       = make_float2(a[0], a[1]);
            *(float2*)(g_p + (size_t)(r0 + 8) * 1024 + c0) = make_float2(a[2], a[3]);
        }
    }
}

// ---------------------------------------------------------------------------
// Fused edge MLP + scatter:
//   h = rna(relu(P[src] + P[snk] + be1)) ; msgs = h @ We2r + be2
//   atomicAdd msgs into g_inc[snk]
// M = B*E = 131072, N = 256, K = 512
__global__ __launch_bounds__(256, 2)
void k_edge2f(const float* __restrict__ be1, const float* __restrict__ be2,
              const int* __restrict__ esrc, const int* __restrict__ esnk)
{
    SMEM_TILES;
    __shared__ int sIdx[2][128];

    GEMM_PROLOG;

    const int rowBase = blockIdx.y * 128;
    const int colBase = blockIdx.x * 128;
    const int b  = rowBase >> 14;
    const int e0 = rowBase & (Ee - 1);

    if (tid < 128)      sIdx[0][tid]       = esrc[e0 + tid];
    else                sIdx[1][tid - 128] = esnk[e0 + tid - 128];
    __syncthreads();

    const float* Pb = g_p + (size_t)b * Nn * 1024;
    const size_t srcRow = (size_t)sIdx[0][ar] * 1024;
    const size_t snkRow = (size_t)sIdx[1][ar] * 1024 + 512;

    float4 u0, u1, v0, v1;

#define ISSUE_EF(k0)                                                     \
    {                                                                    \
        u0 = *(const float4*)(Pb + srcRow + (k0) + akq);                 \
        u1 = *(const float4*)(Pb + srcRow + (k0) + akq + 4);             \
        v0 = *(const float4*)(Pb + snkRow + (k0) + akq);                 \
        v1 = *(const float4*)(Pb + snkRow + (k0) + akq + 4);             \
    }

#define COMMIT_EF(st, k0)                                                \
    {                                                                    \
        float4 b0 = *(const float4*)(be1 + (k0) + akq);                  \
        float4 b1 = *(const float4*)(be1 + (k0) + akq + 4);              \
        uint32_t* dst = (uint32_t*)&As[st][ar][akq];                     \
        dst[0] = f2tf(fmaxf(u0.x + v0.x + b0.x, 0.f));                   \
        dst[1] = f2tf(fmaxf(u0.y + v0.y + b0.y, 0.f));                   \
        dst[2] = f2tf(fmaxf(u0.z + v0.z + b0.z, 0.f));                   \
        dst[3] = f2tf(fmaxf(u0.w + v0.w + b0.w, 0.f));                   \
        dst[4] = f2tf(fmaxf(u1.x + v1.x + b1.x, 0.f));                   \
        dst[5] = f2tf(fmaxf(u1.y + v1.y + b1.y, 0.f));                   \
        dst[6] = f2tf(fmaxf(u1.z + v1.z + b1.z, 0.f));                   \
        dst[7] = f2tf(fmaxf(u1.w + v1.w + b1.w, 0.f));                   \
    }

#define LOADB_EF(st, k0)                                                 \
    _Pragma("unroll") for (int q = 0; q < 2; q++)                        \
        cpa16(B_ADDR(st, bkr, bnq + q * 4),                              \
              g_We2r + (size_t)((k0) + bkr) * MSGm + colBase + bnq + q * 4);

    ISSUE_EF(0);
    LOADB_EF(0, 0);
    CP_COMMIT;
    COMMIT_EF(0, 0);

    for (int it = 0; it < 32; it++) {
        if (it + 1 < 32) {
            ISSUE_EF((it + 1) * 16);
            LOADB_EF((it + 1) & 1, (it + 1) * 16);
            CP_COMMIT;
            CP_WAIT1;
        } else {
            CP_WAIT0;
        }
        __syncthreads();
        COMPUTE(it & 1);
        if (it + 1 < 32) COMMIT_EF((it + 1) & 1, (it + 1) * 16);
        __syncthreads();
    }

    float* incb = g_inc + (size_t)b * Nn * MSGm;
#pragma unroll
    for (int mt = 0; mt < 4; mt++) {
        int r0 = wM + mt * 16 + grp;
        int s0 = sIdx[1][r0], s1 = sIdx[1][r0 + 8];
#pragma unroll
        for (int nt = 0; nt < 4; nt++) {
            int c0 = colBase + wN + nt * 8 + tig * 2;
            float b0 = be2[c0], b1 = be2[c0 + 1];
            float* a = acc[mt][nt];
            float* p0 = incb + (size_t)s0 * MSGm + c0;
            float* p1 = incb + (size_t)s1 * MSGm + c0;
            atomicAdd(p0,     a[0] + b0);
            atomicAdd(p0 + 1, a[1] + b1);
            atomicAdd(p1,     a[2] + b0);
            atomicAdd(p1 + 1, a[3] + b1);
        }
    }
}

// ---------------------------------------------------------------------------
// Node MLP layer 1: g_h2 = rna(relu(concat(g_inc, g_nsr) @ Wn1r + b_n1))
// M = 32768, N = 512, K = 512
__global__ __launch_bounds__(256, 2)
void k_node1(const float* __restrict__ bn1)
{
    SMEM_TILES;
    GEMM_PROLOG;

    const int rowBase = blockIdx.y * 128;
    const int colBase = blockIdx.x * 128;

#define LOAD_N1(st, k0)                                                  \
    {                                                                    \
        _Pragma("unroll") for (int q = 0; q < 2; q++) {                  \
            int kg = (k0) + akq + q * 4;                                 \
            const float* src = (kg < MSGm)                               \
                ? (g_inc + (size_t)(rowBase + ar) * MSGm + kg)           \
                : (g_nsr + (size_t)(rowBase + ar) * Dd + (kg - MSGm));   \
            cpa16(A_ADDR(st, ar, akq + q * 4), src);                     \
        }                                                                \
        _Pragma("unroll") for (int q = 0; q < 2; q++)                    \
            cpa16(B_ADDR(st, bkr, bnq + q * 4),                          \
                  g_Wn1r + (size_t)((k0) + bkr) * Hh + colBase + bnq + q * 4); \
    }

    PIPELINE(32, LOAD_N1);

#pragma unroll
    for (int mt = 0; mt < 4; mt++) {
        int r0 = rowBase + wM + mt * 16 + grp;
#pragma unroll
        for (int nt = 0; nt < 4; nt++) {
            int c0 = colBase + wN + nt * 8 + tig * 2;
            float b0 = bn1[c0], b1 = bn1[c0 + 1];
            float* a = acc[mt][nt];
            *(float2*)(g_h2 + (size_t)r0 * Hh + c0) =
                make_float2(rndf(fmaxf(a[0] + b0, 0.f)), rndf(fmaxf(a[1] + b1, 0.f)));
            *(float2*)(g_h2 + (size_t)(r0 + 8) * Hh + c0) =
                make_float2(rndf(fmaxf(a[2] + b0, 0.f)), rndf(fmaxf(a[3] + b1, 0.f)));
        }
    }
}

// ---------------------------------------------------------------------------
// Node MLP layer 2 + in-place update
// M = 32768, N = 254 (padded 256), K = 512
__global__ __launch_bounds__(256, 2)
void k_node2(const float* __restrict__ bn2)
{
    SMEM_TILES;
    GEMM_PROLOG;

    const int rowBase = blockIdx.y * 128;
    const int colBase = blockIdx.x * 128;

    const float* Ag = g_h2 + (size_t)rowBase * Hh;

#define LOAD_N2(st, k0)                                                  \
    {                                                                    \
        _Pragma("unroll") for (int q = 0; q < 2; q++)                    \
            cpa16(A_ADDR(st, ar, akq + q * 4),                           \
                  Ag + (size_t)ar * Hh + (k0) + akq + q * 4);            \
        _Pragma("unroll") for (int q = 0; q < 2; q++)                    \
            cpa16(B_ADDR(st, bkr, bnq + q * 4),                          \
                  g_Wn2r + (size_t)((k0) + bkr) * 256 + colBase + bnq + q * 4); \
    }

    PIPELINE(32, LOAD_N2);

#pragma unroll
    for (int mt = 0; mt < 4; mt++) {
        int r0 = rowBase + wM + mt * 16 + grp;
#pragma unroll
        for (int nt = 0; nt < 4; nt++) {
            int c0 = colBase + wN + nt * 8 + tig * 2;
            float* a = acc[mt][nt];
#pragma unroll
            for (int h = 0; h < 2; h++) {
                int c = c0 + h;
                if (c < UPDu) {
                    float bb = bn2[c];
                    size_t i0 = (size_t)r0 * Dd + 2 + c;
                    size_t i1 = (size_t)(r0 + 8) * Dd + 2 + c;
                    float v0 = g_ns[i0] + a[h]     + bb;
                    float v1 = g_ns[i1] + a[2 + h] + bb;
                    g_ns[i0] = v0;  g_nsr[i0] = rndf(v0);
                    g_ns[i1] = v1;  g_nsr[i1] = rndf(v1);
                }
            }
        }
    }
}

// ---------------------------------------------------------------------------
// Extraction: out[b,p,d] += sum over n-slice of attn[b,p,n]*ns[b,n,d]
// 8 p's per CTA (8x less g_ns re-read), n-range split 8 ways (512 CTAs).
__global__ __launch_bounds__(256)
void k_extract(const float* __restrict__ attn, float* __restrict__ out)
{
    const int pg = blockIdx.x;   // 0..7 : p group
    const int b  = blockIdx.y;   // 0..7
    const int ns = blockIdx.z;   // 0..7 : n-slice
    const int d  = threadIdx.x;

    const float* nsb = g_ns + (size_t)b * Nn * Dd;

    __shared__ float sa[8][256];
    float acc[8];
#pragma unroll
    for (int pp = 0; pp < 8; pp++) acc[pp] = 0.f;

    for (int t = 0; t < 2; t++) {
        int n0 = ns * 512 + t * 256;
        __syncthreads();
#pragma unroll
        for (int pp = 0; pp < 8; pp++)
            sa[pp][d] = attn[((size_t)b * Pp + pg * 8 + pp) * Nn + n0 + d];
        __syncthreads();
#pragma unroll 4
        for (int n = 0; n < 256; n++) {
            float x = nsb[(size_t)(n0 + n) * Dd + d];
#pragma unroll
            for (int pp = 0; pp < 8; pp++)
                acc[pp] = fmaf(sa[pp][n], x, acc[pp]);
        }
    }

#pragma unroll
    for (int pp = 0; pp < 8; pp++)
        atomicAdd(&out[((size_t)b * Pp + pg * 8 + pp) * Dd + d], acc[pp]);
}

// ---------------------------------------------------------------------------
extern "C" void kernel_launch(void* const* d_in, const int* in_sizes, int n_in,
                              void* d_out, int out_size)
{
    const float* nodes = (const float*)d_in[0];
    const float* attn  = (const float*)d_in[1];
    const float* We1   = (const float*)d_in[2];
    const float* be1   = (const float*)d_in[3];
    const float* We2   = (const float*)d_in[4];
    const float* be2   = (const float*)d_in[5];
    const float* Wn1   = (const float*)d_in[6];
    const float* bn1   = (const float*)d_in[7];
    const float* Wn2   = (const float*)d_in[8];
    const float* bn2   = (const float*)d_in[9];
    const int*   esrc  = (const int*)d_in[10];
    const int*   esnk  = (const int*)d_in[11];
    float* out = (float*)d_out;

    float* dWe2r; cudaGetSymbolAddress((void**)&dWe2r, g_We2r);
    float* dWn1r; cudaGetSymbolAddress((void**)&dWn1r, g_Wn1r);

    // Prologue: combined/rounded weights + state copies
    k_make_we1c<<<(Dd * 1024 + 255) / 256, 256>>>(We1);
    k_round<<<(Hh * MSGm + 255) / 256, 256>>>(We2, dWe2r, Hh * MSGm);
    k_round<<<((Dd + MSGm) * Hh + 255) / 256, 256>>>(Wn1, dWn1r, (Dd + MSGm) * Hh);
    k_round_pad_wn2<<<(Hh * 256 + 255) / 256, 256>>>(Wn2);
    k_copy_ns<<<(Bb * Nn * Dd + 255) / 256, 256>>>(nodes);

    for (int s = 0; s < STEPS; s++) {
        k_zero_inc<<<8192, 256>>>();
        k_pre<<<dim3(1024 / 128, (Bb * Nn) / 128), 256>>>();
        k_edge2f<<<dim3(MSGm / 128, (Bb * Ee) / 128), 256>>>(be1, be2, esrc, esnk);
        k_round_inc<<<(Bb * Nn * MSGm + 255) / 256, 256>>>();
        k_node1<<<dim3(Hh / 128, (Bb * Nn) / 128), 256>>>(bn1);
        k_node2<<<dim3(2, (Bb * Nn) / 128), 256>>>(bn2);
    }

    k_zero_out<<<(Bb * Pp * Dd + 255) / 256, 256>>>(out);
    k_extract<<<dim3(Pp / 8, Bb, 8), 256>>>(attn, out);
}

// round 17
// speedup vs baseline: 1.1780x; 1.0264x over previous
#include <cuda_runtime.h>
#include <cstdint>

// Problem constants (fixed by setup_inputs)
#define Bb   8
#define Nn   4096
#define Ee   16384
#define Pp   64
#define Dd   256
#define Hh   512
#define MSGm 256
#define UPDu 254
#define STEPS 3

#define SKA  20    // A smem row stride (words)
#define SKB  136   // B smem row stride (words)
#define AW3  (3 * 128 * SKA)                 // words in 3-stage A region
#define DSMEM ((AW3 + 3 * 16 * SKB) * 4)     // dynamic smem bytes (56832)

// Scratch (device globals per harness allocation rules)
__device__ __align__(128) float g_ns  [(size_t)Bb * Nn * Dd];    // exact state
__device__ __align__(128) float g_nsr [(size_t)Bb * Nn * Dd];    // tf32-rounded state
__device__ __align__(128) float g_p   [(size_t)Bb * Nn * 1024];  // P = nsr @ [We1_top|We1_bot]
__device__ __align__(128) float g_inc [(size_t)Bb * Nn * MSGm];  // messages (raw fp32)
__device__ __align__(128) float g_h2  [(size_t)Bb * Nn * Hh];    // rounded node hidden
__device__ __align__(128) float g_We1c[(size_t)Dd * 1024];       // combined+rounded W_e1
__device__ __align__(128) float g_We2r[(size_t)Hh * MSGm];
__device__ __align__(128) float g_Wn1r[(size_t)(Dd+MSGm) * Hh];
__device__ __align__(128) float g_Wn2r[(size_t)Hh * 256];        // padded 254 -> 256

// ---------------------------------------------------------------------------
__device__ __forceinline__ uint32_t f2tf(float x) {
    uint32_t u;
    asm("cvt.rna.tf32.f32 %0, %1;" : "=r"(u) : "f"(x));
    return u;
}
__device__ __forceinline__ float rndf(float x) { return __uint_as_float(f2tf(x)); }
__device__ __forceinline__ uint32_t f2tf_bits(uint32_t b) {
    return f2tf(__uint_as_float(b));
}

__device__ __forceinline__ void mma8(float* c, uint32_t a0, uint32_t a1,
                                     uint32_t a2, uint32_t a3,
                                     uint32_t b0, uint32_t b1) {
    asm volatile(
        "mma.sync.aligned.m16n8k8.row.col.f32.tf32.tf32.f32 "
        "{%0,%1,%2,%3}, {%4,%5,%6,%7}, {%8,%9}, {%0,%1,%2,%3};"
        : "+f"(c[0]), "+f"(c[1]), "+f"(c[2]), "+f"(c[3])
        : "r"(a0), "r"(a1), "r"(a2), "r"(a3), "r"(b0), "r"(b1));
}

__device__ __forceinline__ void ldsm4(uint32_t& r0, uint32_t& r1,
                                      uint32_t& r2, uint32_t& r3, uint32_t addr) {
    asm volatile("ldmatrix.sync.aligned.m8n8.x4.shared.b16 {%0,%1,%2,%3}, [%4];"
                 : "=r"(r0), "=r"(r1), "=r"(r2), "=r"(r3) : "r"(addr));
}

__device__ __forceinline__ void cpa16(uint32_t dst, const float* src) {
    asm volatile("cp.async.ca.shared.global [%0], [%1], 16;"
                 :: "r"(dst), "l"(src));
}
#define CP_COMMIT asm volatile("cp.async.commit_group;")
#define CP_WAIT1  asm volatile("cp.async.wait_group 1;")
#define CP_WAIT0  asm volatile("cp.async.wait_group 0;")

// ---------------------------------------------------------------------------
// Prologue / utility kernels
__global__ void k_round(const float* __restrict__ src, float* __restrict__ dst, int n) {
    int i = blockIdx.x * blockDim.x + threadIdx.x;
    if (i < n) dst[i] = rndf(src[i]);
}

__global__ void k_make_we1c(const float* __restrict__ We1) {
    int i = blockIdx.x * blockDim.x + threadIdx.x;
    if (i < Dd * 1024) {
        int k = i >> 10, j = i & 1023;
        float v = (j < Hh) ? We1[k * Hh + j] : We1[(Dd + k) * Hh + (j - Hh)];
        g_We1c[i] = rndf(v);
    }
}

__global__ void k_round_pad_wn2(const float* __restrict__ src) {
    int i = blockIdx.x * blockDim.x + threadIdx.x;
    if (i < Hh * 256) {
        int r = i >> 8, c = i & 255;
        g_Wn2r[i] = (c < UPDu) ? rndf(src[r * UPDu + c]) : 0.f;
    }
}

__global__ void k_copy_ns(const float* __restrict__ src) {
    size_t i = (size_t)blockIdx.x * blockDim.x + threadIdx.x;
    if (i < (size_t)Bb * Nn * Dd) {
        float v = src[i];
        g_ns[i]  = v;
        g_nsr[i] = rndf(v);
    }
}

__global__ void k_zero_inc() {
    size_t i = (size_t)blockIdx.x * blockDim.x + threadIdx.x;
    if (i < ((size_t)Bb * Nn * MSGm) / 4)
        ((float4*)g_inc)[i] = make_float4(0.f, 0.f, 0.f, 0.f);
}

__global__ void k_zero_out(float* __restrict__ out) {
    int i = blockIdx.x * blockDim.x + threadIdx.x;
    if (i < Bb * Pp * Dd) out[i] = 0.f;
}

// ---------------------------------------------------------------------------
// Common index prolog (no smem binding)
#define GEMM_IDX                                                         \
    const int tid  = threadIdx.x;                                        \
    const int lane = tid & 31;                                           \
    const int warp = tid >> 5;                                           \
    const int grp  = lane >> 2;                                          \
    const int tig  = lane & 3;                                           \
    const int wM   = (warp & 1) * 64;                                    \
    const int wN   = (warp >> 1) * 32;                                   \
    const int ar   = tid >> 1;                                           \
    const int akq  = (tid & 1) * 8;                                      \
    const int bkr  = tid >> 4;                                           \
    const int bnq  = (tid & 15) * 8;                                     \
    const int lrow = lane & 15;                                          \
    const int lcol = (lane >> 4) * 4;                                    \
    float acc[4][4][4];                                                  \
    _Pragma("unroll") for (int i = 0; i < 4; i++)                        \
    _Pragma("unroll") for (int j = 0; j < 4; j++)                        \
    _Pragma("unroll") for (int q = 0; q < 4; q++) acc[i][j][q] = 0.f;

#define A_ADDR(st, m, k) (sA + (((st) * 128 + (m)) * SKA + (k)) * 4u)
#define B_ADDR(st, k, n) (sB + (((st) * 16  + (k)) * SKB + (n)) * 4u)

// ---- 2-stage variant (edge2f only; static smem, proven in R16) ----
#define GEMM_PROLOG2                                                     \
    GEMM_IDX;                                                            \
    const uint32_t sA = (uint32_t)__cvta_generic_to_shared(&As[0][0][0]);\
    const uint32_t sB = (uint32_t)__cvta_generic_to_shared(&Bs[0][0][0]);

#define COMPUTE2(st)                                                     \
    _Pragma("unroll") for (int kb = 0; kb < 16; kb += 8) {               \
        uint32_t af[4][4], bf[4][2];                                     \
        _Pragma("unroll") for (int mt = 0; mt < 4; mt++)                 \
            ldsm4(af[mt][0], af[mt][1], af[mt][2], af[mt][3],            \
                  A_ADDR(st, wM + mt * 16 + lrow, kb + lcol));           \
        _Pragma("unroll") for (int nt = 0; nt < 4; nt++) {               \
            int cc = wN + nt * 8 + grp;                                  \
            bf[nt][0] = Bs[st][kb + tig][cc];                            \
            bf[nt][1] = Bs[st][kb + tig + 4][cc];                        \
        }                                                                \
        _Pragma("unroll") for (int mt = 0; mt < 4; mt++)                 \
        _Pragma("unroll") for (int nt = 0; nt < 4; nt++)                 \
            mma8(acc[mt][nt], af[mt][0], af[mt][1], af[mt][2],           \
                 af[mt][3], bf[nt][0], bf[nt][1]);                       \
    }

// ---- 3-stage variant (dynamic smem, single sync per iteration) ----
#define GEMM_PROLOG3                                                     \
    GEMM_IDX;                                                            \
    uint32_t* const BsP = dynsmem + AW3;                                 \
    const uint32_t sA = (uint32_t)__cvta_generic_to_shared(dynsmem);     \
    const uint32_t sB = (uint32_t)__cvta_generic_to_shared(BsP);

#define COMPUTE3_BODY(st, CVTA)                                          \
    _Pragma("unroll") for (int kb = 0; kb < 16; kb += 8) {               \
        uint32_t af[4][4], bf[4][2];                                     \
        _Pragma("unroll") for (int mt = 0; mt < 4; mt++) {               \
            ldsm4(af[mt][0], af[mt][1], af[mt][2], af[mt][3],            \
                  A_ADDR(st, wM + mt * 16 + lrow, kb + lcol));           \
            CVTA(mt);                                                    \
        }                                                                \
        _Pragma("unroll") for (int nt = 0; nt < 4; nt++) {               \
            int cc = wN + nt * 8 + grp;                                  \
            bf[nt][0] = BsP[((st) * 16 + kb + tig) * SKB + cc];          \
            bf[nt][1] = BsP[((st) * 16 + kb + tig + 4) * SKB + cc];      \
        }                                                                \
        _Pragma("unroll") for (int mt = 0; mt < 4; mt++)                 \
        _Pragma("unroll") for (int nt = 0; nt < 4; nt++)                 \
            mma8(acc[mt][nt], af[mt][0], af[mt][1], af[mt][2],           \
                 af[mt][3], bf[nt][0], bf[nt][1]);                       \
    }

#define NOCVT(mt)
#define CVT_AF(mt)                                                       \
    af[mt][0] = f2tf_bits(af[mt][0]); af[mt][1] = f2tf_bits(af[mt][1]);  \
    af[mt][2] = f2tf_bits(af[mt][2]); af[mt][3] = f2tf_bits(af[mt][3]);

#define COMPUTE3(st)    COMPUTE3_BODY(st, NOCVT)
#define COMPUTE3CVT(st) COMPUTE3_BODY(st, CVT_AF)

// 3-stage pipeline: [wait<=1; sync; compute(it%3); load((it+2)%3); commit]
#define PIPELINE3(NITER, LOADER, COMP)                                   \
    LOADER(0, 0);  CP_COMMIT;                                            \
    LOADER(1, 16); CP_COMMIT;                                            \
    for (int it = 0; it < (NITER); it++) {                               \
        if (it < (NITER) - 1) { CP_WAIT1; } else { CP_WAIT0; }           \
        __syncthreads();                                                 \
        COMP(it % 3);                                                    \
        if (it + 2 < (NITER)) {                                          \
            LOADER((it + 2) % 3, (it + 2) * 16);                         \
            CP_COMMIT;                                                   \
        }                                                                \
    }

// ---------------------------------------------------------------------------
// Node-projection GEMM: g_p = g_nsr @ g_We1c   (3-stage)
// M = 32768, N = 1024, K = 256
__global__ __launch_bounds__(256, 2)
void k_pre()
{
    extern __shared__ uint32_t dynsmem[];
    GEMM_PROLOG3;

    const int rowBase = blockIdx.y * 128;
    const int colBase = blockIdx.x * 128;

#define LOAD_P(st, k0)                                                   \
    {                                                                    \
        _Pragma("unroll") for (int q = 0; q < 2; q++)                    \
            cpa16(A_ADDR(st, ar, akq + q * 4),                           \
                  g_nsr + (size_t)(rowBase + ar) * Dd + (k0) + akq + q * 4); \
        _Pragma("unroll") for (int q = 0; q < 2; q++)                    \
            cpa16(B_ADDR(st, bkr, bnq + q * 4),                          \
                  g_We1c + (size_t)((k0) + bkr) * 1024 + colBase + bnq + q * 4); \
    }

    PIPELINE3(16, LOAD_P, COMPUTE3);

#pragma unroll
    for (int mt = 0; mt < 4; mt++) {
        int r0 = rowBase + wM + mt * 16 + grp;
#pragma unroll
        for (int nt = 0; nt < 4; nt++) {
            int c0 = colBase + wN + nt * 8 + tig * 2;
            float* a = acc[mt][nt];
            *(float2*)(g_p + (size_t)r0 * 1024 + c0)       = make_float2(a[0], a[1]);
            *(float2*)(g_p + (size_t)(r0 + 8) * 1024 + c0) = make_float2(a[2], a[3]);
        }
    }
}

// ---------------------------------------------------------------------------
// Fused edge MLP + scatter (2-stage, unchanged from R16):
//   h = rna(relu(P[src] + P[snk] + be1)) ; msgs = h @ We2r + be2
//   atomicAdd msgs into g_inc[snk]
// M = B*E = 131072, N = 256, K = 512
__global__ __launch_bounds__(256, 2)
void k_edge2f(const float* __restrict__ be1, const float* __restrict__ be2,
              const int* __restrict__ esrc, const int* __restrict__ esnk)
{
    __shared__ uint32_t As[2][128][SKA];
    __shared__ uint32_t Bs[2][16][SKB];
    __shared__ int sIdx[2][128];

    GEMM_PROLOG2;

    const int rowBase = blockIdx.y * 128;
    const int colBase = blockIdx.x * 128;
    const int b  = rowBase >> 14;
    const int e0 = rowBase & (Ee - 1);

    if (tid < 128)      sIdx[0][tid]       = esrc[e0 + tid];
    else                sIdx[1][tid - 128] = esnk[e0 + tid - 128];
    __syncthreads();

    const float* Pb = g_p + (size_t)b * Nn * 1024;
    const size_t srcRow = (size_t)sIdx[0][ar] * 1024;
    const size_t snkRow = (size_t)sIdx[1][ar] * 1024 + 512;

    float4 u0, u1, v0, v1;

#define ISSUE_EF(k0)                                                     \
    {                                                                    \
        u0 = *(const float4*)(Pb + srcRow + (k0) + akq);                 \
        u1 = *(const float4*)(Pb + srcRow + (k0) + akq + 4);             \
        v0 = *(const float4*)(Pb + snkRow + (k0) + akq);                 \
        v1 = *(const float4*)(Pb + snkRow + (k0) + akq + 4);             \
    }

#define COMMIT_EF(st, k0)                                                \
    {                                                                    \
        float4 b0 = *(const float4*)(be1 + (k0) + akq);                  \
        float4 b1 = *(const float4*)(be1 + (k0) + akq + 4);              \
        uint32_t* dst = (uint32_t*)&As[st][ar][akq];                     \
        dst[0] = f2tf(fmaxf(u0.x + v0.x + b0.x, 0.f));                   \
        dst[1] = f2tf(fmaxf(u0.y + v0.y + b0.y, 0.f));                   \
        dst[2] = f2tf(fmaxf(u0.z + v0.z + b0.z, 0.f));                   \
        dst[3] = f2tf(fmaxf(u0.w + v0.w + b0.w, 0.f));                   \
        dst[4] = f2tf(fmaxf(u1.x + v1.x + b1.x, 0.f));                   \
        dst[5] = f2tf(fmaxf(u1.y + v1.y + b1.y, 0.f));                   \
        dst[6] = f2tf(fmaxf(u1.z + v1.z + b1.z, 0.f));                   \
        dst[7] = f2tf(fmaxf(u1.w + v1.w + b1.w, 0.f));                   \
    }

#define LOADB_EF(st, k0)                                                 \
    _Pragma("unroll") for (int q = 0; q < 2; q++)                        \
        cpa16(B_ADDR(st, bkr, bnq + q * 4),                              \
              g_We2r + (size_t)((k0) + bkr) * MSGm + colBase + bnq + q * 4);

    ISSUE_EF(0);
    LOADB_EF(0, 0);
    CP_COMMIT;
    COMMIT_EF(0, 0);

    for (int it = 0; it < 32; it++) {
        if (it + 1 < 32) {
            ISSUE_EF((it + 1) * 16);
            LOADB_EF((it + 1) & 1, (it + 1) * 16);
            CP_COMMIT;
            CP_WAIT1;
        } else {
            CP_WAIT0;
        }
        __syncthreads();
        COMPUTE2(it & 1);
        if (it + 1 < 32) COMMIT_EF((it + 1) & 1, (it + 1) * 16);
        __syncthreads();
    }

    float* incb = g_inc + (size_t)b * Nn * MSGm;
#pragma unroll
    for (int mt = 0; mt < 4; mt++) {
        int r0 = wM + mt * 16 + grp;
        int s0 = sIdx[1][r0], s1 = sIdx[1][r0 + 8];
#pragma unroll
        for (int nt = 0; nt < 4; nt++) {
            int c0 = colBase + wN + nt * 8 + tig * 2;
            float b0 = be2[c0], b1 = be2[c0 + 1];
            float* a = acc[mt][nt];
            float* p0 = incb + (size_t)s0 * MSGm + c0;
            float* p1 = incb + (size_t)s1 * MSGm + c0;
            atomicAdd(p0,     a[0] + b0);
            atomicAdd(p0 + 1, a[1] + b1);
            atomicAdd(p1,     a[2] + b0);
            atomicAdd(p1 + 1, a[3] + b1);
        }
    }
}

// ---------------------------------------------------------------------------
// Node MLP layer 1 (3-stage; rna applied to A-fragments after LDSM):
// g_h2 = rna(relu(concat(rna(g_inc), g_nsr) @ Wn1r + b_n1))
// M = 32768, N = 512, K = 512
__global__ __launch_bounds__(256, 2)
void k_node1(const float* __restrict__ bn1)
{
    extern __shared__ uint32_t dynsmem[];
    GEMM_PROLOG3;

    const int rowBase = blockIdx.y * 128;
    const int colBase = blockIdx.x * 128;

#define LOAD_N1(st, k0)                                                  \
    {                                                                    \
        _Pragma("unroll") for (int q = 0; q < 2; q++) {                  \
            int kg = (k0) + akq + q * 4;                                 \
            const float* src = (kg < MSGm)                               \
                ? (g_inc + (size_t)(rowBase + ar) * MSGm + kg)           \
                : (g_nsr + (size_t)(rowBase + ar) * Dd + (kg - MSGm));   \
            cpa16(A_ADDR(st, ar, akq + q * 4), src);                     \
        }                                                                \
        _Pragma("unroll") for (int q = 0; q < 2; q++)                    \
            cpa16(B_ADDR(st, bkr, bnq + q * 4),                          \
                  g_Wn1r + (size_t)((k0) + bkr) * Hh + colBase + bnq + q * 4); \
    }

    PIPELINE3(32, LOAD_N1, COMPUTE3CVT);

#pragma unroll
    for (int mt = 0; mt < 4; mt++) {
        int r0 = rowBase + wM + mt * 16 + grp;
#pragma unroll
        for (int nt = 0; nt < 4; nt++) {
            int c0 = colBase + wN + nt * 8 + tig * 2;
            float b0 = bn1[c0], b1 = bn1[c0 + 1];
            float* a = acc[mt][nt];
            *(float2*)(g_h2 + (size_t)r0 * Hh + c0) =
                make_float2(rndf(fmaxf(a[0] + b0, 0.f)), rndf(fmaxf(a[1] + b1, 0.f)));
            *(float2*)(g_h2 + (size_t)(r0 + 8) * Hh + c0) =
                make_float2(rndf(fmaxf(a[2] + b0, 0.f)), rndf(fmaxf(a[3] + b1, 0.f)));
        }
    }
}

// ---------------------------------------------------------------------------
// Node MLP layer 2 + in-place update (3-stage)
// M = 32768, N = 254 (padded 256), K = 512
__global__ __launch_bounds__(256, 2)
void k_node2(const float* __restrict__ bn2)
{
    extern __shared__ uint32_t dynsmem[];
    GEMM_PROLOG3;

    const int rowBase = blockIdx.y * 128;
    const int colBase = blockIdx.x * 128;

    const float* Ag = g_h2 + (size_t)rowBase * Hh;

#define LOAD_N2(st, k0)                                                  \
    {                                                                    \
        _Pragma("unroll") for (int q = 0; q < 2; q++)                    \
            cpa16(A_ADDR(st, ar, akq + q * 4),                           \
                  Ag + (size_t)ar * Hh + (k0) + akq + q * 4);            \
        _Pragma("unroll") for (int q = 0; q < 2; q++)                    \
            cpa16(B_ADDR(st, bkr, bnq + q * 4),                          \
                  g_Wn2r + (size_t)((k0) + bkr) * 256 + colBase + bnq + q * 4); \
    }

    PIPELINE3(32, LOAD_N2, COMPUTE3);

#pragma unroll
    for (int mt = 0; mt < 4; mt++) {
        int r0 = rowBase + wM + mt * 16 + grp;
#pragma unroll
        for (int nt = 0; nt < 4; nt++) {
            int c0 = colBase + wN + nt * 8 + tig * 2;
            float* a = acc[mt][nt];
#pragma unroll
            for (int h = 0; h < 2; h++) {
                int c = c0 + h;
                if (c < UPDu) {
                    float bb = bn2[c];
                    size_t i0 = (size_t)r0 * Dd + 2 + c;
                    size_t i1 = (size_t)(r0 + 8) * Dd + 2 + c;
                    float v0 = g_ns[i0] + a[h]     + bb;
                    float v1 = g_ns[i1] + a[2 + h] + bb;
                    g_ns[i0] = v0;  g_nsr[i0] = rndf(v0);
                    g_ns[i1] = v1;  g_nsr[i1] = rndf(v1);
                }
            }
        }
    }
}

// ---------------------------------------------------------------------------
// Extraction: out[b,p,d] += sum over n-slice of attn[b,p,n]*ns[b,n,d]
// 8 p's per CTA, n-range split 8 ways (512 CTAs).
__global__ __launch_bounds__(256)
void k_extract(const float* __restrict__ attn, float* __restrict__ out)
{
    const int pg = blockIdx.x;
    const int b  = blockIdx.y;
    const int ns = blockIdx.z;
    const int d  = threadIdx.x;

    const float* nsb = g_ns + (size_t)b * Nn * Dd;

    __shared__ float sa[8][256];
    float acc[8];
#pragma unroll
    for (int pp = 0; pp < 8; pp++) acc[pp] = 0.f;

    for (int t = 0; t < 2; t++) {
        int n0 = ns * 512 + t * 256;
        __syncthreads();
#pragma unroll
        for (int pp = 0; pp < 8; pp++)
            sa[pp][d] = attn[((size_t)b * Pp + pg * 8 + pp) * Nn + n0 + d];
        __syncthreads();
#pragma unroll 4
        for (int n = 0; n < 256; n++) {
            float x = nsb[(size_t)(n0 + n) * Dd + d];
#pragma unroll
            for (int pp = 0; pp < 8; pp++)
                acc[pp] = fmaf(sa[pp][n], x, acc[pp]);
        }
    }

#pragma unroll
    for (int pp = 0; pp < 8; pp++)
        atomicAdd(&out[((size_t)b * Pp + pg * 8 + pp) * Dd + d], acc[pp]);
}

// ---------------------------------------------------------------------------
extern "C" void kernel_launch(void* const* d_in, const int* in_sizes, int n_in,
                              void* d_out, int out_size)
{
    const float* nodes = (const float*)d_in[0];
    const float* attn  = (const float*)d_in[1];
    const float* We1   = (const float*)d_in[2];
    const float* be1   = (const float*)d_in[3];
    const float* We2   = (const float*)d_in[4];
    const float* be2   = (const float*)d_in[5];
    const float* Wn1   = (const float*)d_in[6];
    const float* bn1   = (const float*)d_in[7];
    const float* Wn2   = (const float*)d_in[8];
    const float* bn2   = (const float*)d_in[9];
    const int*   esrc  = (const int*)d_in[10];
    const int*   esnk  = (const int*)d_in[11];
    float* out = (float*)d_out;

    float* dWe2r; cudaGetSymbolAddress((void**)&dWe2r, g_We2r);
    float* dWn1r; cudaGetSymbolAddress((void**)&dWn1r, g_Wn1r);

    // Opt-in to >48KB dynamic smem for the 3-stage kernels (idempotent)
    cudaFuncSetAttribute(k_pre,   cudaFuncAttributeMaxDynamicSharedMemorySize, DSMEM);
    cudaFuncSetAttribute(k_node1, cudaFuncAttributeMaxDynamicSharedMemorySize, DSMEM);
    cudaFuncSetAttribute(k_node2, cudaFuncAttributeMaxDynamicSharedMemorySize, DSMEM);

    // Prologue: combined/rounded weights + state copies
    k_make_we1c<<<(Dd * 1024 + 255) / 256, 256>>>(We1);
    k_round<<<(Hh * MSGm + 255) / 256, 256>>>(We2, dWe2r, Hh * MSGm);
    k_round<<<((Dd + MSGm) * Hh + 255) / 256, 256>>>(Wn1, dWn1r, (Dd + MSGm) * Hh);
    k_round_pad_wn2<<<(Hh * 256 + 255) / 256, 256>>>(Wn2);
    k_copy_ns<<<(Bb * Nn * Dd + 255) / 256, 256>>>(nodes);

    for (int s = 0; s < STEPS; s++) {
        k_zero_inc<<<8192, 256>>>();
        k_pre<<<dim3(1024 / 128, (Bb * Nn) / 128), 256, DSMEM>>>();
        k_edge2f<<<dim3(MSGm / 128, (Bb * Ee) / 128), 256>>>(be1, be2, esrc, esnk);
        k_node1<<<dim3(Hh / 128, (Bb * Nn) / 128), 256, DSMEM>>>(bn1);
        k_node2<<<dim3(2, (Bb * Nn) / 128), 256, DSMEM>>>(bn2);
    }

    k_zero_out<<<(Bb * Pp * Dd + 255) / 256, 256>>>(out);
    k_extract<<<dim3(Pp / 8, Bb, 8), 256>>>(attn, out);
}